// round 14
// baseline (speedup 1.0000x reference)
#include <cuda_runtime.h>
#include <math.h>

#define HID 64
#define MAX_N 100000
#define MAX_E 1600000

// ---------------- device scratch (no allocations allowed) ----------------
// packed per-node gather row: [0:64)=node_proj, [64:128)=node_hidden (51.2MB)
__device__ float g_packed[MAX_N * 128];
__device__ float g_h_new[MAX_N * HID];       // 25.6 MB
// bf16 weight images, pre-swizzled into the smem tile layout:
// tile row stride 256B (128 bf16), 16B chunks, chunk c of row r stored at
// byte r*256 + ((c ^ (r&7))*16).
__device__ uint4 g_Wb_edge[64 * 16];         // W_edge, COLUMN-PERMUTED (see prep)
__device__ uint4 g_Wb_node[64 * 16];         // W_node  [j][k] bf16
__device__ uint4 g_Wb_big[256 * 16];         // fused+interleaved GRU weights

// ---------------- helpers -------------------------------------------------
__device__ __forceinline__ unsigned f2bf2(float lo, float hi) {
    unsigned r;
    asm("cvt.rn.bf16x2.f32 %0, %1, %2;" : "=r"(r) : "f"(hi), "f"(lo));
    return r;
}

__device__ __forceinline__ int swz(int row, int chunk) {
    return row * 256 + ((chunk ^ (row & 7)) << 4);
}

__device__ __forceinline__ void mma16816(float c[4],
                                         unsigned a0, unsigned a1,
                                         unsigned a2, unsigned a3,
                                         unsigned b0, unsigned b1) {
    asm("mma.sync.aligned.m16n8k16.row.col.f32.bf16.bf16.f32 "
        "{%0,%1,%2,%3},{%4,%5,%6,%7},{%8,%9},{%0,%1,%2,%3};"
        : "+f"(c[0]), "+f"(c[1]), "+f"(c[2]), "+f"(c[3])
        : "r"(a0), "r"(a1), "r"(a2), "r"(a3), "r"(b0), "r"(b1));
}

// ---------------- weight prep: bf16 convert + swizzle + fusions -----------
// g_Wb_edge row position p holds ORIGINAL W_edge row o(p):
//   ql=(p>>1)&3, nt=p>>3, b=p&1  ->  o = ql*16 + nt*2 + b
// so quad-lane ql's C-fragment slots (acc[nt][b], cols p=nt*8+ql*2+b) hold
// original output columns [16*ql, 16*ql+16) contiguously.
// g_Wb_big columns are gate-interleaved (see round-11 decode).
__global__ void prep_kernel(const float* __restrict__ W_edge,
                            const float* __restrict__ W_node,
                            const float* __restrict__ W_ih,
                            const float* __restrict__ W_hh) {
    int idx = blockIdx.x * blockDim.x + threadIdx.x;  // one 16B chunk each
    float v[8];
    uint4* dst;
    if (idx < 1024) {
        int p = idx >> 4, c = idx & 15;
        int ql = (p >> 1) & 3, nt = p >> 3, b = p & 1;
        int o = ql * 16 + nt * 2 + b;
        const float* src = W_edge + o * 128 + c * 8;
#pragma unroll
        for (int i = 0; i < 8; i++) v[i] = src[i];
        dst = g_Wb_edge + (p * 16 + (c ^ (p & 7)));
    } else if (idx < 2048) {
        int i2 = idx - 1024;
        int j = i2 >> 4, c = i2 & 15;
        const float* src = W_node + j * 128 + c * 8;
#pragma unroll
        for (int i = 0; i < 8; i++) v[i] = src[i];
        dst = g_Wb_node + (j * 16 + (c ^ (j & 7)));
    } else if (idx < 6144) {
        int i3 = idx - 2048;
        int p = i3 >> 4, c = i3 & 15;
        int half = p >> 7, rem = p & 127;
        int nt = rem >> 3, m = nt >> 1, odd = nt & 1;
        int qq = (rem >> 1) & 3, par = rem & 1;
        int j = half * 32 + m * 4 + qq;
        int o = (odd ? (par ? 192 : 128) : (par ? 64 : 0)) + j;
#pragma unroll
        for (int i = 0; i < 8; i++) {
            int k = c * 8 + i;
            float val = 0.f;
            if (k < 64) {
                if (o < 192) val = W_ih[o * 64 + k];
            } else {
                int kk = k - 64;
                if (o < 128)       val = W_hh[o * 64 + kk];
                else if (o >= 192) val = W_hh[(o - 64) * 64 + kk];
            }
            v[i] = val;
        }
        dst = g_Wb_big + (p * 16 + (c ^ (p & 7)));
    } else {
        return;
    }
    uint4 o4;
    o4.x = f2bf2(v[0], v[1]);
    o4.y = f2bf2(v[2], v[3]);
    o4.z = f2bf2(v[4], v[5]);
    o4.w = f2bf2(v[6], v[7]);
    *dst = o4;
}

// ---------------- node_proj + pack hidden + zero h_new --------------------
__global__ void nodeproj_kernel(const float* __restrict__ nf,
                                const float* __restrict__ hidden, int N) {
    __shared__ __align__(16) char sm[49152];
    char* As = sm;                 // 128 x 256B bf16, swizzled
    char* Bs = sm + 32768;         // 64 x 256B bf16, swizzled
    float* Ms = (float*)sm;        // overlay [128][68] fp32 staging
    int t = threadIdx.x;
    int base = blockIdx.x * 128;

    // A load: one 16B bf16 chunk (8 floats = 2 float4) per iter -> STS.128
#pragma unroll
    for (int i = 0; i < 8; i++) {
        int idx = i * 256 + t;
        int row = idx >> 4, c8 = idx & 15;
        int r = base + row; if (r >= N) r = N - 1;
        const float4* p = (const float4*)(nf + (size_t)r * 128 + c8 * 8);
        float4 v1 = p[0], v2 = p[1];
        uint4 o;
        o.x = f2bf2(v1.x, v1.y); o.y = f2bf2(v1.z, v1.w);
        o.z = f2bf2(v2.x, v2.y); o.w = f2bf2(v2.z, v2.w);
        *(uint4*)(As + swz(row, c8)) = o;
    }
#pragma unroll
    for (int i = 0; i < 4; i++) ((uint4*)Bs)[i * 256 + t] = g_Wb_node[i * 256 + t];

    // hidden copy + h_new zero for this block's rows (independent of GEMM)
#pragma unroll
    for (int i = 0; i < 8; i++) {
        int idx = i * 256 + t;           // 2048 float4 chunks
        int row = idx >> 4, c4 = idx & 15;
        int r = base + row;
        if (r < N) {
            *(float4*)(g_packed + (size_t)r * 128 + 64 + c4 * 4) =
                *(const float4*)(hidden + (size_t)r * 64 + c4 * 4);
            *(float4*)(g_h_new + (size_t)r * 64 + c4 * 4) = make_float4(0.f, 0.f, 0.f, 0.f);
        }
    }
    __syncthreads();

    int lane = t & 31, w = t >> 5;
    int mr = w * 16;
    int qr = lane >> 2, qc = (lane & 3) * 4;
    float acc[8][4];
#pragma unroll
    for (int n = 0; n < 8; n++)
#pragma unroll
        for (int q = 0; q < 4; q++) acc[n][q] = 0.f;

#pragma unroll
    for (int k0 = 0; k0 < 128; k0 += 16) {
        int c0 = k0 >> 3, c1 = c0 + 1;
        unsigned a0 = *(unsigned*)(As + swz(mr + qr, c0) + qc);
        unsigned a1 = *(unsigned*)(As + swz(mr + qr + 8, c0) + qc);
        unsigned a2 = *(unsigned*)(As + swz(mr + qr, c1) + qc);
        unsigned a3 = *(unsigned*)(As + swz(mr + qr + 8, c1) + qc);
#pragma unroll
        for (int nt = 0; nt < 8; nt++) {
            unsigned b0 = *(unsigned*)(Bs + swz(nt * 8 + qr, c0) + qc);
            unsigned b1 = *(unsigned*)(Bs + swz(nt * 8 + qr, c1) + qc);
            mma16816(acc[nt], a0, a1, a2, a3, b0, b1);
        }
    }
    __syncthreads();
#pragma unroll
    for (int nt = 0; nt < 8; nt++) {
        int col = nt * 8 + (lane & 3) * 2;
        *(float2*)(Ms + (mr + qr) * 68 + col)     = make_float2(acc[nt][0], acc[nt][1]);
        *(float2*)(Ms + (mr + qr + 8) * 68 + col) = make_float2(acc[nt][2], acc[nt][3]);
    }
    __syncthreads();
#pragma unroll
    for (int i = 0; i < 8; i++) {
        int idx = i * 256 + t;
        int row = idx >> 4, c4 = idx & 15;
        int r = base + row;
        if (r < N)
            *(float4*)(g_packed + (size_t)r * 128 + c4 * 4) = *(float4*)(Ms + row * 68 + c4 * 4);
    }
}

// ---------------- fused edge kernel ---------------------------------------
// GEMM (proven) + register epilogue with PERMUTED B columns: quad-lane ql
// owns original output cols [16ql,16ql+16) -> float4 gathers, red.v2 scatter.
__global__ void __launch_bounds__(256, 4)
edge_kernel(const float* __restrict__ ef,
            const int* __restrict__ src,
            const int* __restrict__ dst,
            int E) {
    __shared__ __align__(16) char sm[49152];
    char* As = sm;                 // 128 x 256B bf16
    char* Bs = sm + 32768;         // 64 x 256B bf16
    int t = threadIdx.x;
    int lane = t & 31, w = t >> 5;
    int base = blockIdx.x * 128;
    int eclamp = E - 1;

    // ---- phase 0: L1-prefetch this warp's 16 gather rows (64 x 128B) ------
#pragma unroll
    for (int u = lane; u < 64; u += 32) {
        int ei = base + w * 16 + (u >> 2);
        if (ei > eclamp) ei = eclamp;
        int s = __ldg(src + ei);
        const char* gp = (const char*)(g_packed + (size_t)s * 128) + (u & 3) * 128;
        asm volatile("prefetch.global.L1 [%0];" :: "l"(gp));
    }

    // ---- phase 1: A tile load (streaming, STS.128 packed) + B copy --------
#pragma unroll
    for (int i = 0; i < 8; i++) {
        int idx = i * 256 + t;
        int row = idx >> 4, c8 = idx & 15;
        int r = base + row; if (r >= E) r = E - 1;
        const float4* p = (const float4*)(ef + (size_t)r * 128 + c8 * 8);
        float4 v1 = __ldcs(p), v2 = __ldcs(p + 1);
        uint4 o;
        o.x = f2bf2(v1.x, v1.y); o.y = f2bf2(v1.z, v1.w);
        o.z = f2bf2(v2.x, v2.y); o.w = f2bf2(v2.z, v2.w);
        *(uint4*)(As + swz(row, c8)) = o;
    }
#pragma unroll
    for (int i = 0; i < 4; i++) ((uint4*)Bs)[i * 256 + t] = g_Wb_edge[i * 256 + t];
    __syncthreads();

    // ---- GEMM (scalar fragment loads; proven) ------------------------------
    int mr = w * 16;
    int qr = lane >> 2, ql = lane & 3;
    int qc = ql * 4;
    float acc[8][4];
#pragma unroll
    for (int n = 0; n < 8; n++)
#pragma unroll
        for (int q = 0; q < 4; q++) acc[n][q] = 0.f;

#pragma unroll
    for (int k0 = 0; k0 < 128; k0 += 16) {
        int c0 = k0 >> 3, c1 = c0 + 1;
        unsigned a0 = *(unsigned*)(As + swz(mr + qr, c0) + qc);
        unsigned a1 = *(unsigned*)(As + swz(mr + qr + 8, c0) + qc);
        unsigned a2 = *(unsigned*)(As + swz(mr + qr, c1) + qc);
        unsigned a3 = *(unsigned*)(As + swz(mr + qr + 8, c1) + qc);
#pragma unroll
        for (int nt = 0; nt < 8; nt++) {
            unsigned b0 = *(unsigned*)(Bs + swz(nt * 8 + qr, c0) + qc);
            unsigned b1 = *(unsigned*)(Bs + swz(nt * 8 + qr, c1) + qc);
            mma16816(acc[nt], a0, a1, a2, a3, b0, b1);
        }
    }

    // ---- phase 2: register epilogue, quad-per-edge, contiguous cols --------
    // Quad (lanes 4*qr..4*qr+3) owns edges e0=w*16+qr (acc[nt][0,1]) and
    // e0+8 (acc[nt][2,3]); lane ql owns original cols [16ql,16ql+16):
    // acc[nt][b] = col 16ql + nt*2 + b (thanks to the B permutation).
    int ge0 = base + w * 16 + qr;
    int ge1 = ge0 + 8;
    int ce0 = min(ge0, eclamp), ce1 = min(ge1, eclamp);
    int s0 = __ldg(src + ce0), d0 = __ldg(dst + ce0);
    int s1 = __ldg(src + ce1), d1 = __ldg(dst + ce1);

#pragma unroll
    for (int rsel = 0; rsel < 2; rsel++) {
        int s = rsel ? s1 : s0;
        int d = rsel ? d1 : d0;
        int ge = rsel ? ge1 : ge0;
        const int a0i = rsel * 2, a1i = rsel * 2 + 1;
        const float4* pp = (const float4*)(g_packed + (size_t)s * 128 + ql * 16);
        float vx[8], vy[8];
#pragma unroll
        for (int i = 0; i < 4; i++) {
            float4 pv = __ldg(pp + i);
            vx[2 * i]     = acc[2 * i][a0i]     + pv.x;   // col 4i+0
            vy[2 * i]     = acc[2 * i][a1i]     + pv.y;   // col 4i+1
            vx[2 * i + 1] = acc[2 * i + 1][a0i] + pv.z;   // col 4i+2
            vy[2 * i + 1] = acc[2 * i + 1][a1i] + pv.w;   // col 4i+3
        }
        float mx = fmaxf(vx[0], vy[0]);
#pragma unroll
        for (int nt = 1; nt < 8; nt++) mx = fmaxf(mx, fmaxf(vx[nt], vy[nt]));
        mx = fmaxf(mx, __shfl_xor_sync(0xffffffffu, mx, 1));
        mx = fmaxf(mx, __shfl_xor_sync(0xffffffffu, mx, 2));
        float ssum = 0.f;
#pragma unroll
        for (int nt = 0; nt < 8; nt++) {
            vx[nt] = __expf(vx[nt] - mx);
            vy[nt] = __expf(vy[nt] - mx);
            ssum += vx[nt] + vy[nt];
        }
        ssum += __shfl_xor_sync(0xffffffffu, ssum, 1);
        ssum += __shfl_xor_sync(0xffffffffu, ssum, 2);
        float inv = 1.0f / ssum;
        if (ge < E) {
            const float4* hp = (const float4*)(g_packed + (size_t)s * 128 + 64 + ql * 16);
            float* ob = g_h_new + (size_t)d * 64 + ql * 16;
#pragma unroll
            for (int i = 0; i < 4; i++) {
                float4 h = __ldg(hp + i);
                float m0 = h.x * vx[2 * i] * inv;
                float m1 = h.y * vy[2 * i] * inv;
                float m2 = h.z * vx[2 * i + 1] * inv;
                float m3 = h.w * vy[2 * i + 1] * inv;
                // red.v2 pair (finer per-address serialization grain than v4)
                asm volatile("red.global.add.v2.f32 [%0], {%1, %2};"
                             :: "l"(ob + i * 4), "f"(m0), "f"(m1) : "memory");
                asm volatile("red.global.add.v2.f32 [%0], {%1, %2};"
                             :: "l"(ob + i * 4 + 2), "f"(m2), "f"(m3) : "memory");
            }
        }
    }
}

// ---------------- GRU kernel: interleaved gates, register epilogue --------
__global__ void gru_kernel(const float* __restrict__ hidden,
                           const float* __restrict__ b_ih,
                           const float* __restrict__ b_hh,
                           float* __restrict__ out, int N) {
    extern __shared__ __align__(16) char dsm[];
    char* As = dsm;                  // 64 x 256B
    char* Bs = dsm + 16384;          // 256 x 256B
    float* Bias = (float*)(dsm + 81920);  // [4][64]: B_r,B_z,B_i,B_h
    int t = threadIdx.x;
    int base = blockIdx.x * 64;

    if (t < 64) {
        Bias[t]       = b_ih[t]       + b_hh[t];        // r pre-act bias
        Bias[64 + t]  = b_ih[64 + t]  + b_hh[64 + t];   // z
        Bias[128 + t] = b_ih[128 + t];                  // gi_n
        Bias[192 + t] = b_hh[128 + t];                  // gh_n
    }

    // A load: STS.128 packed (8 floats per iter)
#pragma unroll
    for (int i = 0; i < 4; i++) {
        int idx = i * 256 + t;           // 1024 chunks of 8 floats
        int row = idx >> 4, c8 = idx & 15;
        int r = base + row; if (r >= N) r = N - 1;
        const float* p = (c8 < 8) ? (g_h_new + (size_t)r * 64 + c8 * 8)
                                  : (hidden  + (size_t)r * 64 + (c8 - 8) * 8);
        float4 v1 = *(const float4*)p;
        float4 v2 = *(const float4*)(p + 4);
        uint4 o;
        o.x = f2bf2(v1.x, v1.y); o.y = f2bf2(v1.z, v1.w);
        o.z = f2bf2(v2.x, v2.y); o.w = f2bf2(v2.z, v2.w);
        *(uint4*)(As + swz(row, c8)) = o;
    }
#pragma unroll
    for (int i = 0; i < 16; i++) ((uint4*)Bs)[i * 256 + t] = g_Wb_big[i * 256 + t];
    __syncthreads();

    int lane = t & 31, w = t >> 5;
    int mr = (w & 3) * 16;
    int ncb = ((w >> 2) & 1) * 128;   // 8 warps: (w&3)=rows, (w>>2)=col half
    int qr = lane >> 2, qc = (lane & 3) * 4;
    int qq = lane & 3;
    float acc[16][4];
#pragma unroll
    for (int n = 0; n < 16; n++)
#pragma unroll
        for (int q = 0; q < 4; q++) acc[n][q] = 0.f;

#pragma unroll
    for (int k0 = 0; k0 < 128; k0 += 16) {
        int c0 = k0 >> 3, c1 = c0 + 1;
        unsigned a0 = *(unsigned*)(As + swz(mr + qr, c0) + qc);
        unsigned a1 = *(unsigned*)(As + swz(mr + qr + 8, c0) + qc);
        unsigned a2 = *(unsigned*)(As + swz(mr + qr, c1) + qc);
        unsigned a3 = *(unsigned*)(As + swz(mr + qr + 8, c1) + qc);
#pragma unroll
        for (int nt = 0; nt < 16; nt++) {
            unsigned b0 = *(unsigned*)(Bs + swz(ncb + nt * 8 + qr, c0) + qc);
            unsigned b1 = *(unsigned*)(Bs + swz(ncb + nt * 8 + qr, c1) + qc);
            mma16816(acc[nt], a0, a1, a2, a3, b0, b1);
        }
    }

    // register epilogue: per m, thread has (r,z) in acc[2m], (gi,gh) in acc[2m+1]
    int row0 = base + mr + qr;
    int row1 = row0 + 8;
#pragma unroll
    for (int m = 0; m < 8; m++) {
        int j = (ncb >> 2) + m * 4 + qq;     // half*32 + m*4 + qq
        float br = Bias[j], bz = Bias[64 + j];
        float bi = Bias[128 + j], bh = Bias[192 + j];
        if (row0 < N) {
            float pr = acc[2 * m][0] + br;
            float pz = acc[2 * m][1] + bz;
            float pi = acc[2 * m + 1][0] + bi;
            float ph = acc[2 * m + 1][1] + bh;
            float r = 1.0f / (1.0f + __expf(-pr));
            float z = 1.0f / (1.0f + __expf(-pz));
            float ng = tanhf(fmaf(r, ph, pi));
            float h = __ldg(hidden + (size_t)row0 * 64 + j);
            out[(size_t)row0 * 64 + j] = fmaf(1.0f - z, ng, z * h);
        }
        if (row1 < N) {
            float pr = acc[2 * m][2] + br;
            float pz = acc[2 * m][3] + bz;
            float pi = acc[2 * m + 1][2] + bi;
            float ph = acc[2 * m + 1][3] + bh;
            float r = 1.0f / (1.0f + __expf(-pr));
            float z = 1.0f / (1.0f + __expf(-pz));
            float ng = tanhf(fmaf(r, ph, pi));
            float h = __ldg(hidden + (size_t)row1 * 64 + j);
            out[(size_t)row1 * 64 + j] = fmaf(1.0f - z, ng, z * h);
        }
    }
}

// ---------------- launch --------------------------------------------------
extern "C" void kernel_launch(void* const* d_in, const int* in_sizes, int n_in,
                              void* d_out, int out_size) {
    const float* node_feats  = (const float*)d_in[0];
    const float* edge_feats  = (const float*)d_in[1];
    const float* node_hidden = (const float*)d_in[2];
    const int*   src         = (const int*)d_in[3];
    const int*   dst         = (const int*)d_in[4];
    const float* W_edge      = (const float*)d_in[5];
    const float* W_node      = (const float*)d_in[6];
    const float* W_ih        = (const float*)d_in[7];
    const float* W_hh        = (const float*)d_in[8];
    const float* b_ih        = (const float*)d_in[9];
    const float* b_hh        = (const float*)d_in[10];
    float* out = (float*)d_out;

    int E = in_sizes[3];
    int N = in_sizes[2] / HID;

    prep_kernel<<<24, 256>>>(W_edge, W_node, W_ih, W_hh);

    nodeproj_kernel<<<(N + 127) / 128, 256>>>(node_feats, node_hidden, N);

    edge_kernel<<<(E + 127) / 128, 256>>>(edge_feats, src, dst, E);

    static const int GRU_SMEM = 81920 + 1024;     // A+B + bias table
    cudaFuncSetAttribute(gru_kernel, cudaFuncAttributeMaxDynamicSharedMemorySize, GRU_SMEM);
    gru_kernel<<<(N + 63) / 64, 256, GRU_SMEM>>>(node_hidden, b_ih, b_hh, out, N);
}

// round 15
// speedup vs baseline: 1.2536x; 1.2536x over previous
#include <cuda_runtime.h>
#include <math.h>

#define HID 64
#define MAX_N 100000
#define MAX_E 1600000

// ---------------- device scratch (no allocations allowed) ----------------
// packed per-node gather row: [0:64)=node_proj, [64:128)=node_hidden (51.2MB)
__device__ float g_packed[MAX_N * 128];
__device__ float g_h_new[MAX_N * HID];       // 25.6 MB
// bf16 weight images, pre-swizzled into the smem tile layout:
// tile row stride 256B (128 bf16), 16B chunks, chunk c of row r stored at
// byte r*256 + ((c ^ (r&7))*16).
__device__ uint4 g_Wb_edge[64 * 16];         // W_edge  [j][k] bf16
__device__ uint4 g_Wb_node[64 * 16];         // W_node  [j][k] bf16
__device__ uint4 g_Wb_big[256 * 16];         // fused+interleaved GRU weights

// ---------------- helpers -------------------------------------------------
__device__ __forceinline__ unsigned f2bf2(float lo, float hi) {
    unsigned r;
    asm("cvt.rn.bf16x2.f32 %0, %1, %2;" : "=r"(r) : "f"(hi), "f"(lo));
    return r;
}

__device__ __forceinline__ int swz(int row, int chunk) {
    return row * 256 + ((chunk ^ (row & 7)) << 4);
}

__device__ __forceinline__ void mma16816(float c[4],
                                         unsigned a0, unsigned a1,
                                         unsigned a2, unsigned a3,
                                         unsigned b0, unsigned b1) {
    asm("mma.sync.aligned.m16n8k16.row.col.f32.bf16.bf16.f32 "
        "{%0,%1,%2,%3},{%4,%5,%6,%7},{%8,%9},{%0,%1,%2,%3};"
        : "+f"(c[0]), "+f"(c[1]), "+f"(c[2]), "+f"(c[3])
        : "r"(a0), "r"(a1), "r"(a2), "r"(a3), "r"(b0), "r"(b1));
}

// ---------------- weight prep: bf16 convert + swizzle + GRU fusion --------
// g_Wb_big column positions are INTERLEAVED so each thread's MMA accumulators
// hold all 4 gates of one hidden dim (see round-11 decode).
__global__ void prep_kernel(const float* __restrict__ W_edge,
                            const float* __restrict__ W_node,
                            const float* __restrict__ W_ih,
                            const float* __restrict__ W_hh) {
    int idx = blockIdx.x * blockDim.x + threadIdx.x;  // one 16B chunk each
    float v[8];
    uint4* dst;
    if (idx < 1024) {
        int j = idx >> 4, c = idx & 15;
        const float* p = W_edge + j * 128 + c * 8;
#pragma unroll
        for (int i = 0; i < 8; i++) v[i] = p[i];
        dst = g_Wb_edge + (j * 16 + (c ^ (j & 7)));
    } else if (idx < 2048) {
        int i2 = idx - 1024;
        int j = i2 >> 4, c = i2 & 15;
        const float* p = W_node + j * 128 + c * 8;
#pragma unroll
        for (int i = 0; i < 8; i++) v[i] = p[i];
        dst = g_Wb_node + (j * 16 + (c ^ (j & 7)));
    } else if (idx < 6144) {
        int i3 = idx - 2048;
        int p = i3 >> 4, c = i3 & 15;
        int half = p >> 7, rem = p & 127;
        int nt = rem >> 3, m = nt >> 1, odd = nt & 1;
        int qq = (rem >> 1) & 3, par = rem & 1;
        int j = half * 32 + m * 4 + qq;
        int o = (odd ? (par ? 192 : 128) : (par ? 64 : 0)) + j;
#pragma unroll
        for (int i = 0; i < 8; i++) {
            int k = c * 8 + i;
            float val = 0.f;
            if (k < 64) {
                if (o < 192) val = W_ih[o * 64 + k];
            } else {
                int kk = k - 64;
                if (o < 128)       val = W_hh[o * 64 + kk];
                else if (o >= 192) val = W_hh[(o - 64) * 64 + kk];
            }
            v[i] = val;
        }
        dst = g_Wb_big + (p * 16 + (c ^ (p & 7)));
    } else {
        return;
    }
    uint4 o4;
    o4.x = f2bf2(v[0], v[1]);
    o4.y = f2bf2(v[2], v[3]);
    o4.z = f2bf2(v[4], v[5]);
    o4.w = f2bf2(v[6], v[7]);
    *dst = o4;
}

// ---------------- node_proj + pack hidden + zero h_new --------------------
__global__ void __launch_bounds__(256, 4)
nodeproj_kernel(const float* __restrict__ nf,
                const float* __restrict__ hidden, int N) {
    __shared__ __align__(16) char sm[49152];
    char* As = sm;                 // 128 x 256B bf16, swizzled
    char* Bs = sm + 32768;         // 64 x 256B bf16, swizzled
    float* Ms = (float*)sm;        // overlay [128][68] fp32 staging
    int t = threadIdx.x;
    int base = blockIdx.x * 128;

    // A load: one 16B bf16 chunk (8 floats = 2 float4) per iter -> STS.128
#pragma unroll
    for (int i = 0; i < 8; i++) {
        int idx = i * 256 + t;
        int row = idx >> 4, c8 = idx & 15;
        int r = base + row; if (r >= N) r = N - 1;
        const float4* p = (const float4*)(nf + (size_t)r * 128 + c8 * 8);
        float4 v1 = p[0], v2 = p[1];
        uint4 o;
        o.x = f2bf2(v1.x, v1.y); o.y = f2bf2(v1.z, v1.w);
        o.z = f2bf2(v2.x, v2.y); o.w = f2bf2(v2.z, v2.w);
        *(uint4*)(As + swz(row, c8)) = o;
    }
#pragma unroll
    for (int i = 0; i < 4; i++) ((uint4*)Bs)[i * 256 + t] = g_Wb_node[i * 256 + t];

    // hidden copy + h_new zero for this block's rows (independent of GEMM)
#pragma unroll
    for (int i = 0; i < 8; i++) {
        int idx = i * 256 + t;           // 2048 float4 chunks
        int row = idx >> 4, c4 = idx & 15;
        int r = base + row;
        if (r < N) {
            *(float4*)(g_packed + (size_t)r * 128 + 64 + c4 * 4) =
                *(const float4*)(hidden + (size_t)r * 64 + c4 * 4);
            *(float4*)(g_h_new + (size_t)r * 64 + c4 * 4) = make_float4(0.f, 0.f, 0.f, 0.f);
        }
    }
    __syncthreads();

    int lane = t & 31, w = t >> 5;
    int mr = w * 16;
    int qr = lane >> 2, qc = (lane & 3) * 4;
    float acc[8][4];
#pragma unroll
    for (int n = 0; n < 8; n++)
#pragma unroll
        for (int q = 0; q < 4; q++) acc[n][q] = 0.f;

#pragma unroll
    for (int k0 = 0; k0 < 128; k0 += 16) {
        int c0 = k0 >> 3, c1 = c0 + 1;
        unsigned a0 = *(unsigned*)(As + swz(mr + qr, c0) + qc);
        unsigned a1 = *(unsigned*)(As + swz(mr + qr + 8, c0) + qc);
        unsigned a2 = *(unsigned*)(As + swz(mr + qr, c1) + qc);
        unsigned a3 = *(unsigned*)(As + swz(mr + qr + 8, c1) + qc);
#pragma unroll
        for (int nt = 0; nt < 8; nt++) {
            unsigned b0 = *(unsigned*)(Bs + swz(nt * 8 + qr, c0) + qc);
            unsigned b1 = *(unsigned*)(Bs + swz(nt * 8 + qr, c1) + qc);
            mma16816(acc[nt], a0, a1, a2, a3, b0, b1);
        }
    }
    __syncthreads();
#pragma unroll
    for (int nt = 0; nt < 8; nt++) {
        int col = nt * 8 + (lane & 3) * 2;
        *(float2*)(Ms + (mr + qr) * 68 + col)     = make_float2(acc[nt][0], acc[nt][1]);
        *(float2*)(Ms + (mr + qr + 8) * 68 + col) = make_float2(acc[nt][2], acc[nt][3]);
    }
    __syncthreads();
#pragma unroll
    for (int i = 0; i < 8; i++) {
        int idx = i * 256 + t;
        int row = idx >> 4, c4 = idx & 15;
        int r = base + row;
        if (r < N)
            *(float4*)(g_packed + (size_t)r * 128 + c4 * 4) = *(float4*)(Ms + row * 68 + c4 * 4);
    }
}

// ---------------- fused edge kernel ---------------------------------------
// GEMM (proven) + ROUND-12 register epilogue: quad-per-edge, interleaved
// ql*2 + nt*8 column ownership, 8x red.v2 (coalescing-optimal, measured).
__global__ void __launch_bounds__(256, 4)
edge_kernel(const float* __restrict__ ef,
            const int* __restrict__ src,
            const int* __restrict__ dst,
            int E) {
    __shared__ __align__(16) char sm[49152];
    char* As = sm;                 // 128 x 256B bf16
    char* Bs = sm + 32768;         // 64 x 256B bf16
    int t = threadIdx.x;
    int lane = t & 31, w = t >> 5;
    int base = blockIdx.x * 128;
    int eclamp = E - 1;

    // ---- phase 0: L1-prefetch this warp's 16 gather rows (64 x 128B) ------
#pragma unroll
    for (int u = lane; u < 64; u += 32) {
        int ei = base + w * 16 + (u >> 2);
        if (ei > eclamp) ei = eclamp;
        int s = __ldg(src + ei);
        const char* gp = (const char*)(g_packed + (size_t)s * 128) + (u & 3) * 128;
        asm volatile("prefetch.global.L1 [%0];" :: "l"(gp));
    }

    // ---- phase 1: A tile load (streaming, STS.128 packed) + B copy --------
#pragma unroll
    for (int i = 0; i < 8; i++) {
        int idx = i * 256 + t;
        int row = idx >> 4, c8 = idx & 15;
        int r = base + row; if (r >= E) r = E - 1;
        const float4* p = (const float4*)(ef + (size_t)r * 128 + c8 * 8);
        float4 v1 = __ldcs(p), v2 = __ldcs(p + 1);
        uint4 o;
        o.x = f2bf2(v1.x, v1.y); o.y = f2bf2(v1.z, v1.w);
        o.z = f2bf2(v2.x, v2.y); o.w = f2bf2(v2.z, v2.w);
        *(uint4*)(As + swz(row, c8)) = o;
    }
#pragma unroll
    for (int i = 0; i < 4; i++) ((uint4*)Bs)[i * 256 + t] = g_Wb_edge[i * 256 + t];
    __syncthreads();

    // ---- GEMM (scalar fragment loads; proven) ------------------------------
    int mr = w * 16;
    int qr = lane >> 2, ql = lane & 3;
    int qc = ql * 4;
    float acc[8][4];
#pragma unroll
    for (int n = 0; n < 8; n++)
#pragma unroll
        for (int q = 0; q < 4; q++) acc[n][q] = 0.f;

#pragma unroll
    for (int k0 = 0; k0 < 128; k0 += 16) {
        int c0 = k0 >> 3, c1 = c0 + 1;
        unsigned a0 = *(unsigned*)(As + swz(mr + qr, c0) + qc);
        unsigned a1 = *(unsigned*)(As + swz(mr + qr + 8, c0) + qc);
        unsigned a2 = *(unsigned*)(As + swz(mr + qr, c1) + qc);
        unsigned a3 = *(unsigned*)(As + swz(mr + qr + 8, c1) + qc);
#pragma unroll
        for (int nt = 0; nt < 8; nt++) {
            unsigned b0 = *(unsigned*)(Bs + swz(nt * 8 + qr, c0) + qc);
            unsigned b1 = *(unsigned*)(Bs + swz(nt * 8 + qr, c1) + qc);
            mma16816(acc[nt], a0, a1, a2, a3, b0, b1);
        }
    }

    // ---- phase 2: register epilogue, quad-per-edge -------------------------
    // Quad (lanes 4*qr..4*qr+3) owns edges e0=w*16+qr (acc[nt][0,1]) and
    // e0+8 (acc[nt][2,3]); cols nt*8 + ql*2 + {0,1}.
    int ge0 = base + w * 16 + qr;
    int ge1 = ge0 + 8;
    int ce0 = min(ge0, eclamp), ce1 = min(ge1, eclamp);
    int s0 = __ldg(src + ce0), d0 = __ldg(dst + ce0);
    int s1 = __ldg(src + ce1), d1 = __ldg(dst + ce1);

#pragma unroll
    for (int rsel = 0; rsel < 2; rsel++) {
        int s = rsel ? s1 : s0;
        int d = rsel ? d1 : d0;
        int ge = rsel ? ge1 : ge0;
        int a0i = rsel * 2, a1i = rsel * 2 + 1;
        const float2* pp = (const float2*)(g_packed + (size_t)s * 128) + ql;
        const float2* hp = (const float2*)(g_packed + (size_t)s * 128 + 64) + ql;
        float vx[8], vy[8];
#pragma unroll
        for (int nt = 0; nt < 8; nt++) {
            float2 p = __ldg(pp + nt * 4);
            vx[nt] = acc[nt][a0i] + p.x;
            vy[nt] = acc[nt][a1i] + p.y;
        }
        float mx = fmaxf(vx[0], vy[0]);
#pragma unroll
        for (int nt = 1; nt < 8; nt++) mx = fmaxf(mx, fmaxf(vx[nt], vy[nt]));
        mx = fmaxf(mx, __shfl_xor_sync(0xffffffffu, mx, 1));
        mx = fmaxf(mx, __shfl_xor_sync(0xffffffffu, mx, 2));
        float ssum = 0.f;
#pragma unroll
        for (int nt = 0; nt < 8; nt++) {
            vx[nt] = __expf(vx[nt] - mx);
            vy[nt] = __expf(vy[nt] - mx);
            ssum += vx[nt] + vy[nt];
        }
        ssum += __shfl_xor_sync(0xffffffffu, ssum, 1);
        ssum += __shfl_xor_sync(0xffffffffu, ssum, 2);
        float inv = 1.0f / ssum;
        if (ge < E) {
            float* ob = g_h_new + (size_t)d * 64 + ql * 2;
#pragma unroll
            for (int nt = 0; nt < 8; nt++) {
                float2 h = __ldg(hp + nt * 4);
                float m0 = h.x * vx[nt] * inv;
                float m1 = h.y * vy[nt] * inv;
                asm volatile("red.global.add.v2.f32 [%0], {%1, %2};"
                             :: "l"(ob + nt * 8), "f"(m0), "f"(m1) : "memory");
            }
        }
    }
}

// ---------------- GRU kernel: interleaved gates, register epilogue --------
__global__ void gru_kernel(const float* __restrict__ hidden,
                           const float* __restrict__ b_ih,
                           const float* __restrict__ b_hh,
                           float* __restrict__ out, int N) {
    extern __shared__ __align__(16) char dsm[];
    char* As = dsm;                  // 64 x 256B
    char* Bs = dsm + 16384;          // 256 x 256B
    float* Bias = (float*)(dsm + 81920);  // [4][64]: B_r,B_z,B_i,B_h
    int t = threadIdx.x;
    int base = blockIdx.x * 64;

    if (t < 64) {
        Bias[t]       = b_ih[t]       + b_hh[t];        // r pre-act bias
        Bias[64 + t]  = b_ih[64 + t]  + b_hh[64 + t];   // z
        Bias[128 + t] = b_ih[128 + t];                  // gi_n
        Bias[192 + t] = b_hh[128 + t];                  // gh_n
    }

    // A load: STS.128 packed (8 floats per iter)
#pragma unroll
    for (int i = 0; i < 4; i++) {
        int idx = i * 256 + t;           // 1024 chunks of 8 floats
        int row = idx >> 4, c8 = idx & 15;
        int r = base + row; if (r >= N) r = N - 1;
        const float* p = (c8 < 8) ? (g_h_new + (size_t)r * 64 + c8 * 8)
                                  : (hidden  + (size_t)r * 64 + (c8 - 8) * 8);
        float4 v1 = *(const float4*)p;
        float4 v2 = *(const float4*)(p + 4);
        uint4 o;
        o.x = f2bf2(v1.x, v1.y); o.y = f2bf2(v1.z, v1.w);
        o.z = f2bf2(v2.x, v2.y); o.w = f2bf2(v2.z, v2.w);
        *(uint4*)(As + swz(row, c8)) = o;
    }
#pragma unroll
    for (int i = 0; i < 16; i++) ((uint4*)Bs)[i * 256 + t] = g_Wb_big[i * 256 + t];
    __syncthreads();

    int lane = t & 31, w = t >> 5;
    int mr = (w & 3) * 16;
    int ncb = ((w >> 2) & 1) * 128;   // 8 warps: (w&3)=rows, (w>>2)=col half
    int qr = lane >> 2, qc = (lane & 3) * 4;
    int qq = lane & 3;
    float acc[16][4];
#pragma unroll
    for (int n = 0; n < 16; n++)
#pragma unroll
        for (int q = 0; q < 4; q++) acc[n][q] = 0.f;

#pragma unroll
    for (int k0 = 0; k0 < 128; k0 += 16) {
        int c0 = k0 >> 3, c1 = c0 + 1;
        unsigned a0 = *(unsigned*)(As + swz(mr + qr, c0) + qc);
        unsigned a1 = *(unsigned*)(As + swz(mr + qr + 8, c0) + qc);
        unsigned a2 = *(unsigned*)(As + swz(mr + qr, c1) + qc);
        unsigned a3 = *(unsigned*)(As + swz(mr + qr + 8, c1) + qc);
#pragma unroll
        for (int nt = 0; nt < 16; nt++) {
            unsigned b0 = *(unsigned*)(Bs + swz(ncb + nt * 8 + qr, c0) + qc);
            unsigned b1 = *(unsigned*)(Bs + swz(ncb + nt * 8 + qr, c1) + qc);
            mma16816(acc[nt], a0, a1, a2, a3, b0, b1);
        }
    }

    // register epilogue: per m, thread has (r,z) in acc[2m], (gi,gh) in acc[2m+1]
    int row0 = base + mr + qr;
    int row1 = row0 + 8;
#pragma unroll
    for (int m = 0; m < 8; m++) {
        int j = (ncb >> 2) + m * 4 + qq;     // half*32 + m*4 + qq
        float br = Bias[j], bz = Bias[64 + j];
        float bi = Bias[128 + j], bh = Bias[192 + j];
        if (row0 < N) {
            float pr = acc[2 * m][0] + br;
            float pz = acc[2 * m][1] + bz;
            float pi = acc[2 * m + 1][0] + bi;
            float ph = acc[2 * m + 1][1] + bh;
            float r = 1.0f / (1.0f + __expf(-pr));
            float z = 1.0f / (1.0f + __expf(-pz));
            float ng = tanhf(fmaf(r, ph, pi));
            float h = __ldg(hidden + (size_t)row0 * 64 + j);
            out[(size_t)row0 * 64 + j] = fmaf(1.0f - z, ng, z * h);
        }
        if (row1 < N) {
            float pr = acc[2 * m][2] + br;
            float pz = acc[2 * m][3] + bz;
            float pi = acc[2 * m + 1][2] + bi;
            float ph = acc[2 * m + 1][3] + bh;
            float r = 1.0f / (1.0f + __expf(-pr));
            float z = 1.0f / (1.0f + __expf(-pz));
            float ng = tanhf(fmaf(r, ph, pi));
            float h = __ldg(hidden + (size_t)row1 * 64 + j);
            out[(size_t)row1 * 64 + j] = fmaf(1.0f - z, ng, z * h);
        }
    }
}

// ---------------- launch --------------------------------------------------
extern "C" void kernel_launch(void* const* d_in, const int* in_sizes, int n_in,
                              void* d_out, int out_size) {
    const float* node_feats  = (const float*)d_in[0];
    const float* edge_feats  = (const float*)d_in[1];
    const float* node_hidden = (const float*)d_in[2];
    const int*   src         = (const int*)d_in[3];
    const int*   dst         = (const int*)d_in[4];
    const float* W_edge      = (const float*)d_in[5];
    const float* W_node      = (const float*)d_in[6];
    const float* W_ih        = (const float*)d_in[7];
    const float* W_hh        = (const float*)d_in[8];
    const float* b_ih        = (const float*)d_in[9];
    const float* b_hh        = (const float*)d_in[10];
    float* out = (float*)d_out;

    int E = in_sizes[3];
    int N = in_sizes[2] / HID;

    prep_kernel<<<24, 256>>>(W_edge, W_node, W_ih, W_hh);

    nodeproj_kernel<<<(N + 127) / 128, 256>>>(node_feats, node_hidden, N);

    edge_kernel<<<(E + 127) / 128, 256>>>(edge_feats, src, dst, E);

    static const int GRU_SMEM = 81920 + 1024;     // A+B + bias table
    cudaFuncSetAttribute(gru_kernel, cudaFuncAttributeMaxDynamicSharedMemorySize, GRU_SMEM);
    gru_kernel<<<(N + 63) / 64, 256, GRU_SMEM>>>(node_hidden, b_ih, b_hh, out, N);
}

// round 16
// speedup vs baseline: 1.8983x; 1.5142x over previous
#include <cuda_runtime.h>
#include <math.h>

#define HID 64
#define MAX_N 100000
#define MAX_E 1600000

// ---------------- device scratch (no allocations allowed) ----------------
// packed per-node gather row: [0:64)=node_proj, [64:128)=node_hidden (51.2MB)
__device__ float g_packed[MAX_N * 128];
__device__ float g_h_new[MAX_N * HID];       // 25.6 MB
// bf16 weight images, pre-swizzled into the smem tile layout:
// tile row stride 256B (128 bf16), 16B chunks, chunk c of row r stored at
// byte r*256 + ((c ^ (r&7))*16).
__device__ uint4 g_Wb_edge[64 * 16];         // W_edge  [j][k] bf16
__device__ uint4 g_Wb_node[64 * 16];         // W_node  [j][k] bf16
__device__ uint4 g_Wb_big[256 * 16];         // fused+interleaved GRU weights

// ---------------- helpers -------------------------------------------------
__device__ __forceinline__ unsigned f2bf2(float lo, float hi) {
    unsigned r;
    asm("cvt.rn.bf16x2.f32 %0, %1, %2;" : "=r"(r) : "f"(hi), "f"(lo));
    return r;
}

__device__ __forceinline__ int swz(int row, int chunk) {
    return row * 256 + ((chunk ^ (row & 7)) << 4);
}

__device__ __forceinline__ void mma16816(float c[4],
                                         unsigned a0, unsigned a1,
                                         unsigned a2, unsigned a3,
                                         unsigned b0, unsigned b1) {
    asm("mma.sync.aligned.m16n8k16.row.col.f32.bf16.bf16.f32 "
        "{%0,%1,%2,%3},{%4,%5,%6,%7},{%8,%9},{%0,%1,%2,%3};"
        : "+f"(c[0]), "+f"(c[1]), "+f"(c[2]), "+f"(c[3])
        : "r"(a0), "r"(a1), "r"(a2), "r"(a3), "r"(b0), "r"(b1));
}

// ---------------- weight prep: bf16 convert + swizzle + GRU fusion --------
// g_Wb_big column positions are INTERLEAVED so each thread's MMA accumulators
// hold all 4 gates of one hidden dim (see round-11 decode).
__global__ void prep_kernel(const float* __restrict__ W_edge,
                            const float* __restrict__ W_node,
                            const float* __restrict__ W_ih,
                            const float* __restrict__ W_hh) {
    int idx = blockIdx.x * blockDim.x + threadIdx.x;  // one 16B chunk each
    float v[8];
    uint4* dst;
    if (idx < 1024) {
        int j = idx >> 4, c = idx & 15;
        const float* p = W_edge + j * 128 + c * 8;
#pragma unroll
        for (int i = 0; i < 8; i++) v[i] = p[i];
        dst = g_Wb_edge + (j * 16 + (c ^ (j & 7)));
    } else if (idx < 2048) {
        int i2 = idx - 1024;
        int j = i2 >> 4, c = i2 & 15;
        const float* p = W_node + j * 128 + c * 8;
#pragma unroll
        for (int i = 0; i < 8; i++) v[i] = p[i];
        dst = g_Wb_node + (j * 16 + (c ^ (j & 7)));
    } else if (idx < 6144) {
        int i3 = idx - 2048;
        int p = i3 >> 4, c = i3 & 15;
        int half = p >> 7, rem = p & 127;
        int nt = rem >> 3, m = nt >> 1, odd = nt & 1;
        int qq = (rem >> 1) & 3, par = rem & 1;
        int j = half * 32 + m * 4 + qq;
        int o = (odd ? (par ? 192 : 128) : (par ? 64 : 0)) + j;
#pragma unroll
        for (int i = 0; i < 8; i++) {
            int k = c * 8 + i;
            float val = 0.f;
            if (k < 64) {
                if (o < 192) val = W_ih[o * 64 + k];
            } else {
                int kk = k - 64;
                if (o < 128)       val = W_hh[o * 64 + kk];
                else if (o >= 192) val = W_hh[(o - 64) * 64 + kk];
            }
            v[i] = val;
        }
        dst = g_Wb_big + (p * 16 + (c ^ (p & 7)));
    } else {
        return;
    }
    uint4 o4;
    o4.x = f2bf2(v[0], v[1]);
    o4.y = f2bf2(v[2], v[3]);
    o4.z = f2bf2(v[4], v[5]);
    o4.w = f2bf2(v[6], v[7]);
    *dst = o4;
}

// ---------------- node_proj + pack hidden + zero h_new --------------------
__global__ void nodeproj_kernel(const float* __restrict__ nf,
                                const float* __restrict__ hidden, int N) {
    __shared__ __align__(16) char sm[49152];
    char* As = sm;                 // 128 x 256B bf16, swizzled
    char* Bs = sm + 32768;         // 64 x 256B bf16, swizzled
    float* Ms = (float*)sm;        // overlay [128][68] fp32 staging
    int t = threadIdx.x;
    int base = blockIdx.x * 128;

    // A load: one 16B bf16 chunk (8 floats = 2 float4) per iter -> STS.128
#pragma unroll
    for (int i = 0; i < 8; i++) {
        int idx = i * 256 + t;
        int row = idx >> 4, c8 = idx & 15;
        int r = base + row; if (r >= N) r = N - 1;
        const float4* p = (const float4*)(nf + (size_t)r * 128 + c8 * 8);
        float4 v1 = p[0], v2 = p[1];
        uint4 o;
        o.x = f2bf2(v1.x, v1.y); o.y = f2bf2(v1.z, v1.w);
        o.z = f2bf2(v2.x, v2.y); o.w = f2bf2(v2.z, v2.w);
        *(uint4*)(As + swz(row, c8)) = o;
    }
#pragma unroll
    for (int i = 0; i < 4; i++) ((uint4*)Bs)[i * 256 + t] = g_Wb_node[i * 256 + t];

    // hidden copy + h_new zero for this block's rows (independent of GEMM)
#pragma unroll
    for (int i = 0; i < 8; i++) {
        int idx = i * 256 + t;           // 2048 float4 chunks
        int row = idx >> 4, c4 = idx & 15;
        int r = base + row;
        if (r < N) {
            *(float4*)(g_packed + (size_t)r * 128 + 64 + c4 * 4) =
                *(const float4*)(hidden + (size_t)r * 64 + c4 * 4);
            *(float4*)(g_h_new + (size_t)r * 64 + c4 * 4) = make_float4(0.f, 0.f, 0.f, 0.f);
        }
    }
    __syncthreads();

    int lane = t & 31, w = t >> 5;
    int mr = w * 16;
    int qr = lane >> 2, qc = (lane & 3) * 4;
    float acc[8][4];
#pragma unroll
    for (int n = 0; n < 8; n++)
#pragma unroll
        for (int q = 0; q < 4; q++) acc[n][q] = 0.f;

#pragma unroll
    for (int k0 = 0; k0 < 128; k0 += 16) {
        int c0 = k0 >> 3, c1 = c0 + 1;
        unsigned a0 = *(unsigned*)(As + swz(mr + qr, c0) + qc);
        unsigned a1 = *(unsigned*)(As + swz(mr + qr + 8, c0) + qc);
        unsigned a2 = *(unsigned*)(As + swz(mr + qr, c1) + qc);
        unsigned a3 = *(unsigned*)(As + swz(mr + qr + 8, c1) + qc);
#pragma unroll
        for (int nt = 0; nt < 8; nt++) {
            unsigned b0 = *(unsigned*)(Bs + swz(nt * 8 + qr, c0) + qc);
            unsigned b1 = *(unsigned*)(Bs + swz(nt * 8 + qr, c1) + qc);
            mma16816(acc[nt], a0, a1, a2, a3, b0, b1);
        }
    }
    __syncthreads();
#pragma unroll
    for (int nt = 0; nt < 8; nt++) {
        int col = nt * 8 + (lane & 3) * 2;
        *(float2*)(Ms + (mr + qr) * 68 + col)     = make_float2(acc[nt][0], acc[nt][1]);
        *(float2*)(Ms + (mr + qr + 8) * 68 + col) = make_float2(acc[nt][2], acc[nt][3]);
    }
    __syncthreads();
#pragma unroll
    for (int i = 0; i < 8; i++) {
        int idx = i * 256 + t;
        int row = idx >> 4, c4 = idx & 15;
        int r = base + row;
        if (r < N)
            *(float4*)(g_packed + (size_t)r * 128 + c4 * 4) = *(float4*)(Ms + row * 68 + c4 * 4);
    }
}

// ---------------- fused edge kernel ---------------------------------------
// Round-12 champion structure; src/dst loaded ONCE (shared by prefetch and
// phase 2), removing redundant LDGs from the phase-2 dependent chain.
__global__ void __launch_bounds__(256, 4)
edge_kernel(const float* __restrict__ ef,
            const int* __restrict__ src,
            const int* __restrict__ dst,
            int E) {
    __shared__ __align__(16) char sm[49152];
    char* As = sm;                 // 128 x 256B bf16
    char* Bs = sm + 32768;         // 64 x 256B bf16
    int t = threadIdx.x;
    int lane = t & 31, w = t >> 5;
    int base = blockIdx.x * 128;
    int eclamp = E - 1;
    int qr = lane >> 2, ql = lane & 3;
    int qc = ql * 4;

    // ---- phase 0: load this quad's edge indices + L1-prefetch rows --------
    // Quad owns edges ge0 = base + w*16 + qr and ge1 = ge0 + 8.
    int ge0 = base + w * 16 + qr;
    int ge1 = ge0 + 8;
    int ce0 = min(ge0, eclamp), ce1 = min(ge1, eclamp);
    int s0 = __ldg(src + ce0), d0 = __ldg(dst + ce0);
    int s1 = __ldg(src + ce1), d1 = __ldg(dst + ce1);
    {
        const char* gp0 = (const char*)(g_packed + (size_t)s0 * 128) + ql * 128;
        const char* gp1 = (const char*)(g_packed + (size_t)s1 * 128) + ql * 128;
        asm volatile("prefetch.global.L1 [%0];" :: "l"(gp0));
        asm volatile("prefetch.global.L1 [%0];" :: "l"(gp1));
    }

    // ---- phase 1: A tile load (streaming, STS.128 packed) + B copy --------
#pragma unroll
    for (int i = 0; i < 8; i++) {
        int idx = i * 256 + t;
        int row = idx >> 4, c8 = idx & 15;
        int r = base + row; if (r >= E) r = E - 1;
        const float4* p = (const float4*)(ef + (size_t)r * 128 + c8 * 8);
        float4 v1 = __ldcs(p), v2 = __ldcs(p + 1);
        uint4 o;
        o.x = f2bf2(v1.x, v1.y); o.y = f2bf2(v1.z, v1.w);
        o.z = f2bf2(v2.x, v2.y); o.w = f2bf2(v2.z, v2.w);
        *(uint4*)(As + swz(row, c8)) = o;
    }
#pragma unroll
    for (int i = 0; i < 4; i++) ((uint4*)Bs)[i * 256 + t] = g_Wb_edge[i * 256 + t];
    __syncthreads();

    // ---- GEMM (scalar fragment loads; proven) ------------------------------
    int mr = w * 16;
    float acc[8][4];
#pragma unroll
    for (int n = 0; n < 8; n++)
#pragma unroll
        for (int q = 0; q < 4; q++) acc[n][q] = 0.f;

#pragma unroll
    for (int k0 = 0; k0 < 128; k0 += 16) {
        int c0 = k0 >> 3, c1 = c0 + 1;
        unsigned a0 = *(unsigned*)(As + swz(mr + qr, c0) + qc);
        unsigned a1 = *(unsigned*)(As + swz(mr + qr + 8, c0) + qc);
        unsigned a2 = *(unsigned*)(As + swz(mr + qr, c1) + qc);
        unsigned a3 = *(unsigned*)(As + swz(mr + qr + 8, c1) + qc);
#pragma unroll
        for (int nt = 0; nt < 8; nt++) {
            unsigned b0 = *(unsigned*)(Bs + swz(nt * 8 + qr, c0) + qc);
            unsigned b1 = *(unsigned*)(Bs + swz(nt * 8 + qr, c1) + qc);
            mma16816(acc[nt], a0, a1, a2, a3, b0, b1);
        }
    }

    // ---- phase 2: register epilogue, quad-per-edge (round-12 geometry) -----
    // Quad owns edges ge0 (acc[nt][0,1]) and ge1 (acc[nt][2,3]);
    // cols nt*8 + ql*2 + {0,1}.
#pragma unroll
    for (int rsel = 0; rsel < 2; rsel++) {
        int s = rsel ? s1 : s0;
        int d = rsel ? d1 : d0;
        int ge = rsel ? ge1 : ge0;
        int a0i = rsel * 2, a1i = rsel * 2 + 1;
        const float2* pp = (const float2*)(g_packed + (size_t)s * 128) + ql;
        const float2* hp = (const float2*)(g_packed + (size_t)s * 128 + 64) + ql;
        float vx[8], vy[8];
#pragma unroll
        for (int nt = 0; nt < 8; nt++) {
            float2 p = __ldg(pp + nt * 4);
            vx[nt] = acc[nt][a0i] + p.x;
            vy[nt] = acc[nt][a1i] + p.y;
        }
        float mx = fmaxf(vx[0], vy[0]);
#pragma unroll
        for (int nt = 1; nt < 8; nt++) mx = fmaxf(mx, fmaxf(vx[nt], vy[nt]));
        mx = fmaxf(mx, __shfl_xor_sync(0xffffffffu, mx, 1));
        mx = fmaxf(mx, __shfl_xor_sync(0xffffffffu, mx, 2));
        float ssum = 0.f;
#pragma unroll
        for (int nt = 0; nt < 8; nt++) {
            vx[nt] = __expf(vx[nt] - mx);
            vy[nt] = __expf(vy[nt] - mx);
            ssum += vx[nt] + vy[nt];
        }
        ssum += __shfl_xor_sync(0xffffffffu, ssum, 1);
        ssum += __shfl_xor_sync(0xffffffffu, ssum, 2);
        float inv = 1.0f / ssum;
        if (ge < E) {
            float* ob = g_h_new + (size_t)d * 64 + ql * 2;
#pragma unroll
            for (int nt = 0; nt < 8; nt++) {
                float2 h = __ldg(hp + nt * 4);
                float m0 = h.x * vx[nt] * inv;
                float m1 = h.y * vy[nt] * inv;
                asm volatile("red.global.add.v2.f32 [%0], {%1, %2};"
                             :: "l"(ob + nt * 8), "f"(m0), "f"(m1) : "memory");
            }
        }
    }
}

// ---------------- GRU kernel: interleaved gates, register epilogue --------
__global__ void gru_kernel(const float* __restrict__ hidden,
                           const float* __restrict__ b_ih,
                           const float* __restrict__ b_hh,
                           float* __restrict__ out, int N) {
    extern __shared__ __align__(16) char dsm[];
    char* As = dsm;                  // 64 x 256B
    char* Bs = dsm + 16384;          // 256 x 256B
    float* Bias = (float*)(dsm + 81920);  // [4][64]: B_r,B_z,B_i,B_h
    int t = threadIdx.x;
    int base = blockIdx.x * 64;

    if (t < 64) {
        Bias[t]       = b_ih[t]       + b_hh[t];        // r pre-act bias
        Bias[64 + t]  = b_ih[64 + t]  + b_hh[64 + t];   // z
        Bias[128 + t] = b_ih[128 + t];                  // gi_n
        Bias[192 + t] = b_hh[128 + t];                  // gh_n
    }

    // A load: STS.128 packed (8 floats per iter)
#pragma unroll
    for (int i = 0; i < 4; i++) {
        int idx = i * 256 + t;           // 1024 chunks of 8 floats
        int row = idx >> 4, c8 = idx & 15;
        int r = base + row; if (r >= N) r = N - 1;
        const float* p = (c8 < 8) ? (g_h_new + (size_t)r * 64 + c8 * 8)
                                  : (hidden  + (size_t)r * 64 + (c8 - 8) * 8);
        float4 v1 = *(const float4*)p;
        float4 v2 = *(const float4*)(p + 4);
        uint4 o;
        o.x = f2bf2(v1.x, v1.y); o.y = f2bf2(v1.z, v1.w);
        o.z = f2bf2(v2.x, v2.y); o.w = f2bf2(v2.z, v2.w);
        *(uint4*)(As + swz(row, c8)) = o;
    }
#pragma unroll
    for (int i = 0; i < 16; i++) ((uint4*)Bs)[i * 256 + t] = g_Wb_big[i * 256 + t];
    __syncthreads();

    int lane = t & 31, w = t >> 5;
    int mr = (w & 3) * 16;
    int ncb = ((w >> 2) & 1) * 128;   // 8 warps: (w&3)=rows, (w>>2)=col half
    int qr = lane >> 2, qc = (lane & 3) * 4;
    int qq = lane & 3;
    float acc[16][4];
#pragma unroll
    for (int n = 0; n < 16; n++)
#pragma unroll
        for (int q = 0; q < 4; q++) acc[n][q] = 0.f;

#pragma unroll
    for (int k0 = 0; k0 < 128; k0 += 16) {
        int c0 = k0 >> 3, c1 = c0 + 1;
        unsigned a0 = *(unsigned*)(As + swz(mr + qr, c0) + qc);
        unsigned a1 = *(unsigned*)(As + swz(mr + qr + 8, c0) + qc);
        unsigned a2 = *(unsigned*)(As + swz(mr + qr, c1) + qc);
        unsigned a3 = *(unsigned*)(As + swz(mr + qr + 8, c1) + qc);
#pragma unroll
        for (int nt = 0; nt < 16; nt++) {
            unsigned b0 = *(unsigned*)(Bs + swz(ncb + nt * 8 + qr, c0) + qc);
            unsigned b1 = *(unsigned*)(Bs + swz(ncb + nt * 8 + qr, c1) + qc);
            mma16816(acc[nt], a0, a1, a2, a3, b0, b1);
        }
    }

    // register epilogue: per m, thread has (r,z) in acc[2m], (gi,gh) in acc[2m+1]
    int row0 = base + mr + qr;
    int row1 = row0 + 8;
#pragma unroll
    for (int m = 0; m < 8; m++) {
        int j = (ncb >> 2) + m * 4 + qq;     // half*32 + m*4 + qq
        float br = Bias[j], bz = Bias[64 + j];
        float bi = Bias[128 + j], bh = Bias[192 + j];
        if (row0 < N) {
            float pr = acc[2 * m][0] + br;
            float pz = acc[2 * m][1] + bz;
            float pi = acc[2 * m + 1][0] + bi;
            float ph = acc[2 * m + 1][1] + bh;
            float r = 1.0f / (1.0f + __expf(-pr));
            float z = 1.0f / (1.0f + __expf(-pz));
            float ng = tanhf(fmaf(r, ph, pi));
            float h = __ldg(hidden + (size_t)row0 * 64 + j);
            out[(size_t)row0 * 64 + j] = fmaf(1.0f - z, ng, z * h);
        }
        if (row1 < N) {
            float pr = acc[2 * m][2] + br;
            float pz = acc[2 * m][3] + bz;
            float pi = acc[2 * m + 1][2] + bi;
            float ph = acc[2 * m + 1][3] + bh;
            float r = 1.0f / (1.0f + __expf(-pr));
            float z = 1.0f / (1.0f + __expf(-pz));
            float ng = tanhf(fmaf(r, ph, pi));
            float h = __ldg(hidden + (size_t)row1 * 64 + j);
            out[(size_t)row1 * 64 + j] = fmaf(1.0f - z, ng, z * h);
        }
    }
}

// ---------------- launch --------------------------------------------------
extern "C" void kernel_launch(void* const* d_in, const int* in_sizes, int n_in,
                              void* d_out, int out_size) {
    const float* node_feats  = (const float*)d_in[0];
    const float* edge_feats  = (const float*)d_in[1];
    const float* node_hidden = (const float*)d_in[2];
    const int*   src         = (const int*)d_in[3];
    const int*   dst         = (const int*)d_in[4];
    const float* W_edge      = (const float*)d_in[5];
    const float* W_node      = (const float*)d_in[6];
    const float* W_ih        = (const float*)d_in[7];
    const float* W_hh        = (const float*)d_in[8];
    const float* b_ih        = (const float*)d_in[9];
    const float* b_hh        = (const float*)d_in[10];
    float* out = (float*)d_out;

    int E = in_sizes[3];
    int N = in_sizes[2] / HID;

    prep_kernel<<<24, 256>>>(W_edge, W_node, W_ih, W_hh);

    nodeproj_kernel<<<(N + 127) / 128, 256>>>(node_feats, node_hidden, N);

    edge_kernel<<<(E + 127) / 128, 256>>>(edge_feats, src, dst, E);

    static const int GRU_SMEM = 81920 + 1024;     // A+B + bias table
    cudaFuncSetAttribute(gru_kernel, cudaFuncAttributeMaxDynamicSharedMemorySize, GRU_SMEM);
    gru_kernel<<<(N + 63) / 64, 256, GRU_SMEM>>>(node_hidden, b_ih, b_hh, out, N);
}

// round 17
// speedup vs baseline: 2.1380x; 1.1263x over previous
#include <cuda_runtime.h>
#include <math.h>

#define HID 64
#define MAX_N 100000
#define MAX_E 1600000

// ---------------- device scratch (no allocations allowed) ----------------
// packed per-node gather row: [0:64)=node_proj, [64:128)=node_hidden (51.2MB)
__device__ float g_packed[MAX_N * 128];
__device__ float g_h_new[MAX_N * HID];       // 25.6 MB
// bf16 weight images, pre-swizzled into the smem tile layout:
// tile row stride 256B (128 bf16), 16B chunks, chunk c of row r stored at
// byte r*256 + ((c ^ (r&7))*16).
__device__ uint4 g_Wb_edge[64 * 16];         // W_edge, QUAD-CONTIG PERMUTED
__device__ uint4 g_Wb_node[64 * 16];         // W_node  [j][k] bf16
__device__ uint4 g_Wb_big[256 * 16];         // fused+interleaved GRU weights

// ---------------- helpers -------------------------------------------------
__device__ __forceinline__ unsigned f2bf2(float lo, float hi) {
    unsigned r;
    asm("cvt.rn.bf16x2.f32 %0, %1, %2;" : "=r"(r) : "f"(hi), "f"(lo));
    return r;
}

__device__ __forceinline__ int swz(int row, int chunk) {
    return row * 256 + ((chunk ^ (row & 7)) << 4);
}

__device__ __forceinline__ void mma16816(float c[4],
                                         unsigned a0, unsigned a1,
                                         unsigned a2, unsigned a3,
                                         unsigned b0, unsigned b1) {
    asm("mma.sync.aligned.m16n8k16.row.col.f32.bf16.bf16.f32 "
        "{%0,%1,%2,%3},{%4,%5,%6,%7},{%8,%9},{%0,%1,%2,%3};"
        : "+f"(c[0]), "+f"(c[1]), "+f"(c[2]), "+f"(c[3])
        : "r"(a0), "r"(a1), "r"(a2), "r"(a3), "r"(b0), "r"(b1));
}

// ---------------- weight prep: bf16 convert + swizzle + fusions -----------
// g_Wb_edge QUAD-CONTIGUOUS permutation: B position p = nt*8 + ql*2 + b
// holds original W_edge output column o = (nt>>1)*16 + ql*4 + (nt&1)*2 + b.
// => lane ql's acc slots {acc[2g][b], acc[2g+1][b]} hold original columns
//    g*16 + ql*4 + {0,1,2,3}: 4 CONTIGUOUS floats per lane, 64B per quad.
// g_Wb_big columns are gate-interleaved (see round-11 decode).
__global__ void prep_kernel(const float* __restrict__ W_edge,
                            const float* __restrict__ W_node,
                            const float* __restrict__ W_ih,
                            const float* __restrict__ W_hh) {
    int idx = blockIdx.x * blockDim.x + threadIdx.x;  // one 16B chunk each
    float v[8];
    uint4* dst;
    if (idx < 1024) {
        int p = idx >> 4, c = idx & 15;
        int nt = p >> 3, ql = (p >> 1) & 3, b = p & 1;
        int o = (nt >> 1) * 16 + ql * 4 + (nt & 1) * 2 + b;
        const float* src = W_edge + o * 128 + c * 8;
#pragma unroll
        for (int i = 0; i < 8; i++) v[i] = src[i];
        dst = g_Wb_edge + (p * 16 + (c ^ (p & 7)));
    } else if (idx < 2048) {
        int i2 = idx - 1024;
        int j = i2 >> 4, c = i2 & 15;
        const float* src = W_node + j * 128 + c * 8;
#pragma unroll
        for (int i = 0; i < 8; i++) v[i] = src[i];
        dst = g_Wb_node + (j * 16 + (c ^ (j & 7)));
    } else if (idx < 6144) {
        int i3 = idx - 2048;
        int p = i3 >> 4, c = i3 & 15;
        int half = p >> 7, rem = p & 127;
        int nt = rem >> 3, m = nt >> 1, odd = nt & 1;
        int qq = (rem >> 1) & 3, par = rem & 1;
        int j = half * 32 + m * 4 + qq;
        int o = (odd ? (par ? 192 : 128) : (par ? 64 : 0)) + j;
#pragma unroll
        for (int i = 0; i < 8; i++) {
            int k = c * 8 + i;
            float val = 0.f;
            if (k < 64) {
                if (o < 192) val = W_ih[o * 64 + k];
            } else {
                int kk = k - 64;
                if (o < 128)       val = W_hh[o * 64 + kk];
                else if (o >= 192) val = W_hh[(o - 64) * 64 + kk];
            }
            v[i] = val;
        }
        dst = g_Wb_big + (p * 16 + (c ^ (p & 7)));
    } else {
        return;
    }
    uint4 o4;
    o4.x = f2bf2(v[0], v[1]);
    o4.y = f2bf2(v[2], v[3]);
    o4.z = f2bf2(v[4], v[5]);
    o4.w = f2bf2(v[6], v[7]);
    *dst = o4;
}

// ---------------- node_proj + pack hidden + zero h_new --------------------
__global__ void nodeproj_kernel(const float* __restrict__ nf,
                                const float* __restrict__ hidden, int N) {
    __shared__ __align__(16) char sm[49152];
    char* As = sm;                 // 128 x 256B bf16, swizzled
    char* Bs = sm + 32768;         // 64 x 256B bf16, swizzled
    float* Ms = (float*)sm;        // overlay [128][68] fp32 staging
    int t = threadIdx.x;
    int base = blockIdx.x * 128;

    // A load: one 16B bf16 chunk (8 floats = 2 float4) per iter -> STS.128
#pragma unroll
    for (int i = 0; i < 8; i++) {
        int idx = i * 256 + t;
        int row = idx >> 4, c8 = idx & 15;
        int r = base + row; if (r >= N) r = N - 1;
        const float4* p = (const float4*)(nf + (size_t)r * 128 + c8 * 8);
        float4 v1 = p[0], v2 = p[1];
        uint4 o;
        o.x = f2bf2(v1.x, v1.y); o.y = f2bf2(v1.z, v1.w);
        o.z = f2bf2(v2.x, v2.y); o.w = f2bf2(v2.z, v2.w);
        *(uint4*)(As + swz(row, c8)) = o;
    }
#pragma unroll
    for (int i = 0; i < 4; i++) ((uint4*)Bs)[i * 256 + t] = g_Wb_node[i * 256 + t];

    // hidden copy + h_new zero for this block's rows (independent of GEMM)
#pragma unroll
    for (int i = 0; i < 8; i++) {
        int idx = i * 256 + t;           // 2048 float4 chunks
        int row = idx >> 4, c4 = idx & 15;
        int r = base + row;
        if (r < N) {
            *(float4*)(g_packed + (size_t)r * 128 + 64 + c4 * 4) =
                *(const float4*)(hidden + (size_t)r * 64 + c4 * 4);
            *(float4*)(g_h_new + (size_t)r * 64 + c4 * 4) = make_float4(0.f, 0.f, 0.f, 0.f);
        }
    }
    __syncthreads();

    int lane = t & 31, w = t >> 5;
    int mr = w * 16;
    int qr = lane >> 2, qc = (lane & 3) * 4;
    float acc[8][4];
#pragma unroll
    for (int n = 0; n < 8; n++)
#pragma unroll
        for (int q = 0; q < 4; q++) acc[n][q] = 0.f;

#pragma unroll
    for (int k0 = 0; k0 < 128; k0 += 16) {
        int c0 = k0 >> 3, c1 = c0 + 1;
        unsigned a0 = *(unsigned*)(As + swz(mr + qr, c0) + qc);
        unsigned a1 = *(unsigned*)(As + swz(mr + qr + 8, c0) + qc);
        unsigned a2 = *(unsigned*)(As + swz(mr + qr, c1) + qc);
        unsigned a3 = *(unsigned*)(As + swz(mr + qr + 8, c1) + qc);
#pragma unroll
        for (int nt = 0; nt < 8; nt++) {
            unsigned b0 = *(unsigned*)(Bs + swz(nt * 8 + qr, c0) + qc);
            unsigned b1 = *(unsigned*)(Bs + swz(nt * 8 + qr, c1) + qc);
            mma16816(acc[nt], a0, a1, a2, a3, b0, b1);
        }
    }
    __syncthreads();
#pragma unroll
    for (int nt = 0; nt < 8; nt++) {
        int col = nt * 8 + (lane & 3) * 2;
        *(float2*)(Ms + (mr + qr) * 68 + col)     = make_float2(acc[nt][0], acc[nt][1]);
        *(float2*)(Ms + (mr + qr + 8) * 68 + col) = make_float2(acc[nt][2], acc[nt][3]);
    }
    __syncthreads();
#pragma unroll
    for (int i = 0; i < 8; i++) {
        int idx = i * 256 + t;
        int row = idx >> 4, c4 = idx & 15;
        int r = base + row;
        if (r < N)
            *(float4*)(g_packed + (size_t)r * 128 + c4 * 4) = *(float4*)(Ms + row * 68 + c4 * 4);
    }
}

// ---------------- fused edge kernel ---------------------------------------
// GEMM (proven) + register epilogue with QUAD-CONTIGUOUS permuted B:
// lane ql owns cols g*16+ql*4+{0..3} per group g -> float4 gathers and
// red.add.v4 with each quad covering one contiguous 64B span per warp-op.
__global__ void __launch_bounds__(256, 4)
edge_kernel(const float* __restrict__ ef,
            const int* __restrict__ src,
            const int* __restrict__ dst,
            int E) {
    __shared__ __align__(16) char sm[49152];
    char* As = sm;                 // 128 x 256B bf16
    char* Bs = sm + 32768;         // 64 x 256B bf16
    int t = threadIdx.x;
    int lane = t & 31, w = t >> 5;
    int base = blockIdx.x * 128;
    int eclamp = E - 1;
    int qr = lane >> 2, ql = lane & 3;
    int qc = ql * 4;

    // ---- phase 0: load this quad's edge indices + L1-prefetch rows --------
    int ge0 = base + w * 16 + qr;
    int ge1 = ge0 + 8;
    int ce0 = min(ge0, eclamp), ce1 = min(ge1, eclamp);
    int s0 = __ldg(src + ce0), d0 = __ldg(dst + ce0);
    int s1 = __ldg(src + ce1), d1 = __ldg(dst + ce1);
    {
        const char* gp0 = (const char*)(g_packed + (size_t)s0 * 128) + ql * 128;
        const char* gp1 = (const char*)(g_packed + (size_t)s1 * 128) + ql * 128;
        asm volatile("prefetch.global.L1 [%0];" :: "l"(gp0));
        asm volatile("prefetch.global.L1 [%0];" :: "l"(gp1));
    }

    // ---- phase 1: A tile load (streaming, STS.128 packed) + B copy --------
#pragma unroll
    for (int i = 0; i < 8; i++) {
        int idx = i * 256 + t;
        int row = idx >> 4, c8 = idx & 15;
        int r = base + row; if (r >= E) r = E - 1;
        const float4* p = (const float4*)(ef + (size_t)r * 128 + c8 * 8);
        float4 v1 = __ldcs(p), v2 = __ldcs(p + 1);
        uint4 o;
        o.x = f2bf2(v1.x, v1.y); o.y = f2bf2(v1.z, v1.w);
        o.z = f2bf2(v2.x, v2.y); o.w = f2bf2(v2.z, v2.w);
        *(uint4*)(As + swz(row, c8)) = o;
    }
#pragma unroll
    for (int i = 0; i < 4; i++) ((uint4*)Bs)[i * 256 + t] = g_Wb_edge[i * 256 + t];
    __syncthreads();

    // ---- GEMM (scalar fragment loads; proven) ------------------------------
    int mr = w * 16;
    float acc[8][4];
#pragma unroll
    for (int n = 0; n < 8; n++)
#pragma unroll
        for (int q = 0; q < 4; q++) acc[n][q] = 0.f;

#pragma unroll
    for (int k0 = 0; k0 < 128; k0 += 16) {
        int c0 = k0 >> 3, c1 = c0 + 1;
        unsigned a0 = *(unsigned*)(As + swz(mr + qr, c0) + qc);
        unsigned a1 = *(unsigned*)(As + swz(mr + qr + 8, c0) + qc);
        unsigned a2 = *(unsigned*)(As + swz(mr + qr, c1) + qc);
        unsigned a3 = *(unsigned*)(As + swz(mr + qr + 8, c1) + qc);
#pragma unroll
        for (int nt = 0; nt < 8; nt++) {
            unsigned b0 = *(unsigned*)(Bs + swz(nt * 8 + qr, c0) + qc);
            unsigned b1 = *(unsigned*)(Bs + swz(nt * 8 + qr, c1) + qc);
            mma16816(acc[nt], a0, a1, a2, a3, b0, b1);
        }
    }

    // ---- phase 2: register epilogue, quad-per-edge, quad-contiguous --------
    // Lane ql holds original cols g*16 + ql*4 + {0,1,2,3} in
    // {acc[2g][b], acc[2g+1][b]} -> float4 gathers + red.add.v4; each quad's
    // 4 lanes cover one contiguous 64B span per warp-op.
#pragma unroll
    for (int rsel = 0; rsel < 2; rsel++) {
        int s = rsel ? s1 : s0;
        int d = rsel ? d1 : d0;
        int ge = rsel ? ge1 : ge0;
        int a0i = rsel * 2, a1i = rsel * 2 + 1;
        const float4* pp = (const float4*)(g_packed + (size_t)s * 128) + ql;
        float vx[8], vy[8];
#pragma unroll
        for (int g = 0; g < 4; g++) {
            float4 pv = __ldg(pp + g * 4);
            vx[2 * g]     = acc[2 * g][a0i]     + pv.x;   // col g*16+ql*4+0
            vy[2 * g]     = acc[2 * g][a1i]     + pv.y;   // +1
            vx[2 * g + 1] = acc[2 * g + 1][a0i] + pv.z;   // +2
            vy[2 * g + 1] = acc[2 * g + 1][a1i] + pv.w;   // +3
        }
        float mx = fmaxf(vx[0], vy[0]);
#pragma unroll
        for (int nt = 1; nt < 8; nt++) mx = fmaxf(mx, fmaxf(vx[nt], vy[nt]));
        mx = fmaxf(mx, __shfl_xor_sync(0xffffffffu, mx, 1));
        mx = fmaxf(mx, __shfl_xor_sync(0xffffffffu, mx, 2));
        float ssum = 0.f;
#pragma unroll
        for (int nt = 0; nt < 8; nt++) {
            vx[nt] = __expf(vx[nt] - mx);
            vy[nt] = __expf(vy[nt] - mx);
            ssum += vx[nt] + vy[nt];
        }
        ssum += __shfl_xor_sync(0xffffffffu, ssum, 1);
        ssum += __shfl_xor_sync(0xffffffffu, ssum, 2);
        float inv = 1.0f / ssum;
        if (ge < E) {
            const float4* hp = (const float4*)(g_packed + (size_t)s * 128 + 64) + ql;
            float* ob = g_h_new + (size_t)d * 64 + ql * 4;
#pragma unroll
            for (int g = 0; g < 4; g++) {
                float4 hv = __ldg(hp + g * 4);
                float m0 = hv.x * vx[2 * g] * inv;
                float m1 = hv.y * vy[2 * g] * inv;
                float m2 = hv.z * vx[2 * g + 1] * inv;
                float m3 = hv.w * vy[2 * g + 1] * inv;
                asm volatile("red.global.add.v4.f32 [%0], {%1, %2, %3, %4};"
                             :: "l"(ob + g * 16), "f"(m0), "f"(m1), "f"(m2), "f"(m3)
                             : "memory");
            }
        }
    }
}

// ---------------- GRU kernel: interleaved gates, register epilogue --------
__global__ void gru_kernel(const float* __restrict__ hidden,
                           const float* __restrict__ b_ih,
                           const float* __restrict__ b_hh,
                           float* __restrict__ out, int N) {
    extern __shared__ __align__(16) char dsm[];
    char* As = dsm;                  // 64 x 256B
    char* Bs = dsm + 16384;          // 256 x 256B
    float* Bias = (float*)(dsm + 81920);  // [4][64]: B_r,B_z,B_i,B_h
    int t = threadIdx.x;
    int base = blockIdx.x * 64;

    if (t < 64) {
        Bias[t]       = b_ih[t]       + b_hh[t];        // r pre-act bias
        Bias[64 + t]  = b_ih[64 + t]  + b_hh[64 + t];   // z
        Bias[128 + t] = b_ih[128 + t];                  // gi_n
        Bias[192 + t] = b_hh[128 + t];                  // gh_n
    }

    // A load: STS.128 packed (8 floats per iter)
#pragma unroll
    for (int i = 0; i < 4; i++) {
        int idx = i * 256 + t;           // 1024 chunks of 8 floats
        int row = idx >> 4, c8 = idx & 15;
        int r = base + row; if (r >= N) r = N - 1;
        const float* p = (c8 < 8) ? (g_h_new + (size_t)r * 64 + c8 * 8)
                                  : (hidden  + (size_t)r * 64 + (c8 - 8) * 8);
        float4 v1 = *(const float4*)p;
        float4 v2 = *(const float4*)(p + 4);
        uint4 o;
        o.x = f2bf2(v1.x, v1.y); o.y = f2bf2(v1.z, v1.w);
        o.z = f2bf2(v2.x, v2.y); o.w = f2bf2(v2.z, v2.w);
        *(uint4*)(As + swz(row, c8)) = o;
    }
#pragma unroll
    for (int i = 0; i < 16; i++) ((uint4*)Bs)[i * 256 + t] = g_Wb_big[i * 256 + t];
    __syncthreads();

    int lane = t & 31, w = t >> 5;
    int mr = (w & 3) * 16;
    int ncb = ((w >> 2) & 1) * 128;   // 8 warps: (w&3)=rows, (w>>2)=col half
    int qr = lane >> 2, qc = (lane & 3) * 4;
    int qq = lane & 3;
    float acc[16][4];
#pragma unroll
    for (int n = 0; n < 16; n++)
#pragma unroll
        for (int q = 0; q < 4; q++) acc[n][q] = 0.f;

#pragma unroll
    for (int k0 = 0; k0 < 128; k0 += 16) {
        int c0 = k0 >> 3, c1 = c0 + 1;
        unsigned a0 = *(unsigned*)(As + swz(mr + qr, c0) + qc);
        unsigned a1 = *(unsigned*)(As + swz(mr + qr + 8, c0) + qc);
        unsigned a2 = *(unsigned*)(As + swz(mr + qr, c1) + qc);
        unsigned a3 = *(unsigned*)(As + swz(mr + qr + 8, c1) + qc);
#pragma unroll
        for (int nt = 0; nt < 16; nt++) {
            unsigned b0 = *(unsigned*)(Bs + swz(ncb + nt * 8 + qr, c0) + qc);
            unsigned b1 = *(unsigned*)(Bs + swz(ncb + nt * 8 + qr, c1) + qc);
            mma16816(acc[nt], a0, a1, a2, a3, b0, b1);
        }
    }

    // register epilogue: per m, thread has (r,z) in acc[2m], (gi,gh) in acc[2m+1]
    int row0 = base + mr + qr;
    int row1 = row0 + 8;
#pragma unroll
    for (int m = 0; m < 8; m++) {
        int j = (ncb >> 2) + m * 4 + qq;     // half*32 + m*4 + qq
        float br = Bias[j], bz = Bias[64 + j];
        float bi = Bias[128 + j], bh = Bias[192 + j];
        if (row0 < N) {
            float pr = acc[2 * m][0] + br;
            float pz = acc[2 * m][1] + bz;
            float pi = acc[2 * m + 1][0] + bi;
            float ph = acc[2 * m + 1][1] + bh;
            float r = 1.0f / (1.0f + __expf(-pr));
            float z = 1.0f / (1.0f + __expf(-pz));
            float ng = tanhf(fmaf(r, ph, pi));
            float h = __ldg(hidden + (size_t)row0 * 64 + j);
            out[(size_t)row0 * 64 + j] = fmaf(1.0f - z, ng, z * h);
        }
        if (row1 < N) {
            float pr = acc[2 * m][2] + br;
            float pz = acc[2 * m][3] + bz;
            float pi = acc[2 * m + 1][2] + bi;
            float ph = acc[2 * m + 1][3] + bh;
            float r = 1.0f / (1.0f + __expf(-pr));
            float z = 1.0f / (1.0f + __expf(-pz));
            float ng = tanhf(fmaf(r, ph, pi));
            float h = __ldg(hidden + (size_t)row1 * 64 + j);
            out[(size_t)row1 * 64 + j] = fmaf(1.0f - z, ng, z * h);
        }
    }
}

// ---------------- launch --------------------------------------------------
extern "C" void kernel_launch(void* const* d_in, const int* in_sizes, int n_in,
                              void* d_out, int out_size) {
    const float* node_feats  = (const float*)d_in[0];
    const float* edge_feats  = (const float*)d_in[1];
    const float* node_hidden = (const float*)d_in[2];
    const int*   src         = (const int*)d_in[3];
    const int*   dst         = (const int*)d_in[4];
    const float* W_edge      = (const float*)d_in[5];
    const float* W_node      = (const float*)d_in[6];
    const float* W_ih        = (const float*)d_in[7];
    const float* W_hh        = (const float*)d_in[8];
    const float* b_ih        = (const float*)d_in[9];
    const float* b_hh        = (const float*)d_in[10];
    float* out = (float*)d_out;

    int E = in_sizes[3];
    int N = in_sizes[2] / HID;

    prep_kernel<<<24, 256>>>(W_edge, W_node, W_ih, W_hh);

    nodeproj_kernel<<<(N + 127) / 128, 256>>>(node_feats, node_hidden, N);

    edge_kernel<<<(E + 127) / 128, 256>>>(edge_feats, src, dst, E);

    static const int GRU_SMEM = 81920 + 1024;     // A+B + bias table
    cudaFuncSetAttribute(gru_kernel, cudaFuncAttributeMaxDynamicSharedMemorySize, GRU_SMEM);
    gru_kernel<<<(N + 63) / 64, 256, GRU_SMEM>>>(node_hidden, b_ih, b_hh, out, N);
}